// round 15
// baseline (speedup 1.0000x reference)
#include <cuda_runtime.h>
#include <cuda_bf16.h>
#include <cstdint>

// Plane2Depth: out[b,0,H,W] = 1 / max( s*(p*u + q*v + r), 0.1 )
// [p,q,r,s] = Wmat @ feat[b,:,H/4,W/4];  norm cancels algebraically.
//
// R14: WARP-AUTONOMOUS tiles. CTA = ONE warp (32 thr, 2KB smem) owning a
// 32-pixel segment of one input row. No __syncthreads anywhere — only
// __syncwarp. Each warp: 4 coalesced LDG -> matvec -> 16 out/lane ->
// 4 STS.128 -> lane0 ships 4 x 512B cp.async.bulk and drains. 32 CTA
// slots/SM = 32 fully independent warps whose load/MUFU/store/drain phases
// interleave; CTA slots churn fast (drain is only 2KB).
//   grid (6, 192, 16) = 18432 one-warp CTAs (~125 per SM).

#define IN_H   192
#define IN_W   192
#define BATCH  16
#define OUT_HW 768          // 192*4
#define PLANE  (IN_H * IN_W)
#define SEGS   6            // 32-pixel segments per input row

__global__ __launch_bounds__(32)
void plane2depth_kernel(const float* __restrict__ feat,
                        const float4* __restrict__ Wmat,
                        float* __restrict__ out)
{
    __shared__ __align__(16) float sm[4][128];   // 2048 B: 4 sub-rows x 128 cols

    const int lane = threadIdx.x;   // pixel within segment (0..31)
    const int seg  = blockIdx.x;    // segment within row (0..5)
    const int h    = blockIdx.y;    // input row
    const int b    = blockIdx.z;    // batch

    // ---- load 4 channels of this pixel (one 128B line per channel) ----
    const float* fp = feat + (size_t)b * 4 * PLANE + (size_t)h * IN_W
                           + seg * 32 + lane;
    float f0 = fp[0];
    float f1 = fp[PLANE];
    float f2 = fp[2 * PLANE];
    float f3 = fp[3 * PLANE];

    // ---- W matrix: 4 vector loads, uniform broadcast, L1-resident ----
    float4 m0 = __ldg(Wmat + 0);
    float4 m1 = __ldg(Wmat + 1);
    float4 m2 = __ldg(Wmat + 2);
    float4 m3 = __ldg(Wmat + 3);

    float p = fmaf(m0.x, f0, fmaf(m0.y, f1, fmaf(m0.z, f2, m0.w * f3)));
    float q = fmaf(m1.x, f0, fmaf(m1.y, f1, fmaf(m1.z, f2, m1.w * f3)));
    float r = fmaf(m2.x, f0, fmaf(m2.y, f1, fmaf(m2.z, f2, m2.w * f3)));
    float s = fmaf(m3.x, f0, fmaf(m3.y, f1, fmaf(m3.z, f2, m3.w * f3)));

    // fold s:  d = sp*u + sq*v + sr
    float sp = s * p, sq = s * q, sr = s * r;

    const float DMIN = 0.1f;   // 1.0 / MAX_DEPTH
    float pu0 = sp * -0.375f;
    float pu1 = sp * -0.125f;
    float pu2 = -pu1;          // u symmetry
    float pu3 = -pu0;

    float* smr = &sm[0][4 * lane];
#pragma unroll
    for (int j = 0; j < 4; j++) {            // output sub-row (v index)
        float vj   = (float)j * 0.25f - 0.375f;
        float base = fmaf(sq, vj, sr);
        float4 o;
        float d;
        d = pu0 + base; d = fmaxf(d, DMIN); o.x = __fdividef(1.0f, d);
        d = pu1 + base; d = fmaxf(d, DMIN); o.y = __fdividef(1.0f, d);
        d = pu2 + base; d = fmaxf(d, DMIN); o.z = __fdividef(1.0f, d);
        d = pu3 + base; d = fmaxf(d, DMIN); o.w = __fdividef(1.0f, d);
        *(float4*)(smr + (size_t)j * 128) = o;   // STS.128, conflict-free
    }

    __syncwarp();   // all 32 lanes' STS done before lane 0 ships the tile

    if (lane == 0) {
        uint32_t saddr;
        asm volatile("{ .reg .u64 t; cvta.to.shared.u64 t, %1; cvt.u32.u64 %0, t; }"
                     : "=r"(saddr) : "l"(&sm[0][0]));
        asm volatile("fence.proxy.async.shared::cta;" ::: "memory");
        // 4 sub-row segments, 512B each, contiguous in GMEM per sub-row
        float* dst0 = out + ((size_t)b * OUT_HW + (size_t)(4 * h)) * OUT_HW
                          + (size_t)(seg * 128);
#pragma unroll
        for (int j = 0; j < 4; j++) {
            asm volatile("cp.async.bulk.global.shared::cta.bulk_group [%0], [%1], %2;"
                         :: "l"(dst0 + (size_t)j * OUT_HW),
                            "r"(saddr + j * 512), "r"(512) : "memory");
        }
        asm volatile("cp.async.bulk.commit_group;" ::: "memory");
        asm volatile("cp.async.bulk.wait_group 0;" ::: "memory");
    }
}

extern "C" void kernel_launch(void* const* d_in, const int* in_sizes, int n_in,
                              void* d_out, int out_size)
{
    const float*  feat = (const float*)d_in[0];    // (16,4,192,192) f32
    const float4* Wmat = (const float4*)d_in[1];   // (4,4) f32
    float* out = (float*)d_out;                    // (16,1,768,768) f32

    dim3 grid(SEGS, IN_H, BATCH);   // 6 x 192 x 16 = 18432 one-warp CTAs
    dim3 block(32);
    plane2depth_kernel<<<grid, block>>>(feat, Wmat, out);
}

// round 16
// speedup vs baseline: 1.1376x; 1.1376x over previous
#include <cuda_runtime.h>
#include <cuda_bf16.h>
#include <cstdint>

// Plane2Depth: out[b,0,H,W] = 1 / max( s*(p*u + q*v + r), 0.1 )
// [p,q,r,s] = Wmat @ feat[b,:,H/4,W/4];  norm cancels algebraically.
//
// R15: persistent CTAs + double-buffered TMA INPUT pipeline.
//  - 768 CTAs x 192 thr, each owns exactly 4 tiles (tile = one input row).
//  - input arrives via cp.async.bulk global->shared (4 x 768B per tile,
//    mbarrier complete_tx) prefetched 2 tiles deep: warps NEVER issue an
//    input LDG and never stall on input latency in steady state.
//  - output: proven bulk-store path; out-buffer recycled via
//    cp.async.bulk.wait_group.read <=1 (read-done is enough to reuse smem).
//  - smem ~30KB: in 2x3KB, out 2x12KB, 2 mbarriers.

#define IN_H   192
#define IN_W   192
#define BATCH  16
#define OUT_HW 768          // 192*4
#define PLANE  (IN_H * IN_W)
#define NCTA   768          // tiles_total / 4
#define OUT_TILE_BYTES (4 * OUT_HW * 4)   // 12288
#define IN_TILE_BYTES  (4 * IN_W * 4)     // 3072

struct SmemLayout {
    __align__(128) float in[2][4][IN_W];        // 2 x 3072 B
    __align__(128) float outb[2][4][OUT_HW];    // 2 x 12288 B
    __align__(16)  unsigned long long mbar[2];
};

__device__ __forceinline__ uint32_t smem_u32(const void* p) {
    uint32_t a;
    asm("{ .reg .u64 t; cvta.to.shared.u64 t, %1; cvt.u32.u64 %0, t; }"
        : "=r"(a) : "l"(p));
    return a;
}

__global__ __launch_bounds__(IN_W)
void plane2depth_kernel(const float* __restrict__ feat,
                        const float4* __restrict__ Wmat,
                        float* __restrict__ out)
{
    __shared__ SmemLayout sm;

    const int tid = threadIdx.x;    // input column (0..191)
    const int cta = blockIdx.x;     // first tile index; tiles cta + k*NCTA

    const uint32_t mb0 = smem_u32(&sm.mbar[0]);
    const uint32_t mb1 = smem_u32(&sm.mbar[1]);
    const uint32_t in0 = smem_u32(&sm.in[0][0][0]);
    const uint32_t ob0 = smem_u32(&sm.outb[0][0][0]);

    if (tid == 0) {
        asm volatile("mbarrier.init.shared::cta.b64 [%0], 1;" :: "r"(mb0) : "memory");
        asm volatile("mbarrier.init.shared::cta.b64 [%0], 1;" :: "r"(mb1) : "memory");
    }
    __syncthreads();

    // ---- issue_load(stage s, tile T): tid 0 only ----
    auto issue_load = [&](int s, int T) {
        int b = T / IN_H;
        int h = T - b * IN_H;
        const char* src = (const char*)(feat + (size_t)b * 4 * PLANE
                                             + (size_t)h * IN_W);
        uint32_t mb  = s ? mb1 : mb0;
        uint32_t dst = in0 + s * IN_TILE_BYTES;
        asm volatile("mbarrier.arrive.expect_tx.shared::cta.b64 _, [%0], %1;"
                     :: "r"(mb), "r"((uint32_t)IN_TILE_BYTES) : "memory");
#pragma unroll
        for (int c = 0; c < 4; c++) {
            asm volatile(
              "cp.async.bulk.shared::cta.global.mbarrier::complete_tx::bytes "
              "[%0], [%1], %2, [%3];"
              :: "r"(dst + c * (IN_W * 4)),
                 "l"(src + (size_t)c * PLANE * 4),
                 "r"(IN_W * 4), "r"(mb) : "memory");
        }
    };

    // prologue: prefetch tiles k=0 (stage0) and k=1 (stage1)
    if (tid == 0) {
        issue_load(0, cta);
        issue_load(1, cta + NCTA);
    }

    // ---- W matrix (uniform broadcast, L1-resident) ----
    float4 m0 = __ldg(Wmat + 0);
    float4 m1 = __ldg(Wmat + 1);
    float4 m2 = __ldg(Wmat + 2);
    float4 m3 = __ldg(Wmat + 3);

    const float DMIN = 0.1f;   // 1.0 / MAX_DEPTH

#pragma unroll
    for (int k = 0; k < 4; k++) {
        const int s     = k & 1;
        const int phase = k >> 1;           // stage s used at k and k+2
        const uint32_t mb = s ? mb1 : mb0;

        // wait for this tile's input (acquire)
        asm volatile(
            "{\n\t.reg .pred P;\n"
            "WL%=:\n\t"
            "mbarrier.try_wait.parity.acquire.cta.shared::cta.b64 P, [%0], %1, 0x989680;\n\t"
            "@!P bra WL%=;\n\t}"
            :: "r"(mb), "r"((uint32_t)phase) : "memory");

        // ---- compute from smem ----
        float f0 = sm.in[s][0][tid];
        float f1 = sm.in[s][1][tid];
        float f2 = sm.in[s][2][tid];
        float f3 = sm.in[s][3][tid];

        float p = fmaf(m0.x, f0, fmaf(m0.y, f1, fmaf(m0.z, f2, m0.w * f3)));
        float q = fmaf(m1.x, f0, fmaf(m1.y, f1, fmaf(m1.z, f2, m1.w * f3)));
        float r = fmaf(m2.x, f0, fmaf(m2.y, f1, fmaf(m2.z, f2, m2.w * f3)));
        float s4 = fmaf(m3.x, f0, fmaf(m3.y, f1, fmaf(m3.z, f2, m3.w * f3)));

        float sp = s4 * p, sq = s4 * q, sr = s4 * r;
        float pu0 = sp * -0.375f, pu1 = sp * -0.125f;
        float pu2 = -pu1,         pu3 = -pu0;

        float o[4][4];
#pragma unroll
        for (int j = 0; j < 4; j++) {
            float vj   = (float)j * 0.25f - 0.375f;
            float base = fmaf(sq, vj, sr);
            float d;
            d = pu0 + base; d = fmaxf(d, DMIN); o[j][0] = __fdividef(1.0f, d);
            d = pu1 + base; d = fmaxf(d, DMIN); o[j][1] = __fdividef(1.0f, d);
            d = pu2 + base; d = fmaxf(d, DMIN); o[j][2] = __fdividef(1.0f, d);
            d = pu3 + base; d = fmaxf(d, DMIN); o[j][3] = __fdividef(1.0f, d);
        }

        // out-buffer s reusable once the bulk store from iter k-2 has READ it
        if (k >= 2 && tid == 0)
            asm volatile("cp.async.bulk.wait_group.read 1;" ::: "memory");
        __syncthreads();   // (a) out[s] free for all; (b) all LDS of in[s] done

        // prefetch tile k+2 into in[s] (overwrite safe after the barrier)
        if (k + 2 < 4 && tid == 0)
            issue_load(s, cta + (k + 2) * NCTA);

        // stage results to smem
        float* smr = &sm.outb[s][0][4 * tid];
#pragma unroll
        for (int j = 0; j < 4; j++)
            *(float4*)(smr + (size_t)j * OUT_HW) = *(float4*)&o[j][0];

        __syncthreads();   // STS complete before the bulk engine reads

        if (tid == 0) {
            int T = cta + k * NCTA;
            int b = T / IN_H;
            int h = T - b * IN_H;
            float* dst = out + ((size_t)b * OUT_HW + (size_t)(4 * h)) * OUT_HW;
            asm volatile("fence.proxy.async.shared::cta;" ::: "memory");
            asm volatile("cp.async.bulk.global.shared::cta.bulk_group [%0], [%1], %2;"
                         :: "l"(dst), "r"(ob0 + s * OUT_TILE_BYTES),
                            "r"((int)OUT_TILE_BYTES) : "memory");
            asm volatile("cp.async.bulk.commit_group;" ::: "memory");
        }
    }

    // final drain: thread 0 pins the CTA until all bulk stores complete
    if (tid == 0)
        asm volatile("cp.async.bulk.wait_group 0;" ::: "memory");
}

extern "C" void kernel_launch(void* const* d_in, const int* in_sizes, int n_in,
                              void* d_out, int out_size)
{
    const float*  feat = (const float*)d_in[0];    // (16,4,192,192) f32
    const float4* Wmat = (const float4*)d_in[1];   // (4,4) f32
    float* out = (float*)d_out;                    // (16,1,768,768) f32

    plane2depth_kernel<<<NCTA, IN_W>>>(feat, Wmat, out);   // 768 x 192
}